// round 9
// baseline (speedup 1.0000x reference)
#include <cuda_runtime.h>
#include <cuda_bf16.h>
#include <mma.h>
#include <math.h>
#include <stdint.h>

using namespace nvcuda;

#define EMB   768
#define MROWS 1024
#define NN    128
#define KK    128
#define XROWS (3*EMB+2)   // 2306

// ---------------- device scratch ----------------
__device__ __nv_bfloat16 g_WaHi[KK * 2 * EMB];   // [k][e] row-major
__device__ __nv_bfloat16 g_WaLo[KK * 2 * EMB];
__device__ __nv_bfloat16 g_XHi[(size_t)MROWS * XROWS * NN];  // ~604 MB
__device__ __nv_bfloat16 g_XLo[(size_t)MROWS * XROWS * NN];
__device__ float g_Wc [EMB * EMB];
__device__ __nv_bfloat16 g_WcHi[EMB * EMB];
__device__ __nv_bfloat16 g_WcLo[EMB * EMB];
__device__ float g_bc [EMB];
__device__ __nv_bfloat16 g_PHi[(size_t)MROWS * 3 * EMB];
__device__ __nv_bfloat16 g_PLo[(size_t)MROWS * 3 * EMB];
__device__ float g_Z  [(size_t)MROWS * 3 * EMB];

// ---------------- helpers ----------------
__device__ __forceinline__ uint32_t cvta_smem(const void* p) {
    uint32_t a;
    asm("{ .reg .u64 t; cvta.to.shared.u64 t, %1; cvt.u32.u64 %0, t; }" : "=r"(a) : "l"(p));
    return a;
}
__device__ __forceinline__ float tanh_fast(float x) {
    float y;
    asm("tanh.approx.f32 %0, %1;" : "=f"(y) : "f"(x));
    return y;
}
__device__ __forceinline__ void cp16(uint32_t dst, const void* src) {
    asm volatile("cp.async.cg.shared.global [%0], [%1], 16;" :: "r"(dst), "l"(src) : "memory");
}
__device__ __forceinline__ void cp_commit() {
    asm volatile("cp.async.commit_group;" ::: "memory");
}
__device__ __forceinline__ void cp_wait2() {
    asm volatile("cp.async.wait_group 2;" ::: "memory");
}

// ---------------- 0) split Wa ----------------
__global__ void k_split(const float* __restrict__ Wa) {
    int i = blockIdx.x * 256 + threadIdx.x;
    if (i < KK * 2 * EMB) {
        float x = Wa[i];
        __nv_bfloat16 h = __float2bfloat16(x);
        g_WaHi[i] = h;
        g_WaLo[i] = __float2bfloat16(x - __bfloat162float(h));
    }
}

// ---------------- 0b) split X (streaming, BW-bound) ----------------
__global__ void k_xsplit(const float4* __restrict__ X4) {
    size_t total = (size_t)MROWS * XROWS * NN / 4;
    uint2* outH = (uint2*)g_XHi;
    uint2* outL = (uint2*)g_XLo;
    for (size_t i = (size_t)blockIdx.x * blockDim.x + threadIdx.x; i < total;
         i += (size_t)gridDim.x * blockDim.x) {
        float4 v = __ldg(X4 + i);
        __nv_bfloat16 h0 = __float2bfloat16(v.x);
        __nv_bfloat16 h1 = __float2bfloat16(v.y);
        __nv_bfloat16 h2 = __float2bfloat16(v.z);
        __nv_bfloat16 h3 = __float2bfloat16(v.w);
        __nv_bfloat162 hA(h0, h1), hB(h2, h3);
        __nv_bfloat162 lA(__float2bfloat16(v.x - __bfloat162float(h0)),
                          __float2bfloat16(v.y - __bfloat162float(h1)));
        __nv_bfloat162 lB(__float2bfloat16(v.z - __bfloat162float(h2)),
                          __float2bfloat16(v.w - __bfloat162float(h3)));
        uint2 H, L;
        H.x = *(uint32_t*)&hA; H.y = *(uint32_t*)&hB;
        L.x = *(uint32_t*)&lA; L.y = *(uint32_t*)&lB;
        outH[i] = H;
        outL[i] = L;
    }
}

// ---------------- 1) Wc = W2 @ W1 ----------------
__global__ void k_wc(const float* __restrict__ W1, const float* __restrict__ W2) {
    __shared__ float As[64][17];
    __shared__ float Bs[16][65];
    int i0 = blockIdx.y * 64, e0 = blockIdx.x * 64;
    int tx = threadIdx.x & 15, ty = threadIdx.x >> 4;
    float acc[4][4];
#pragma unroll
    for (int i = 0; i < 4; i++)
#pragma unroll
        for (int j = 0; j < 4; j++) acc[i][j] = 0.f;

    for (int t0 = 0; t0 < EMB; t0 += 16) {
        __syncthreads();
        int idx = threadIdx.x;
#pragma unroll
        for (int rep = 0; rep < 4; rep++, idx += 256) {
            int r = idx >> 4, c = idx & 15;
            As[r][c] = W2[(size_t)(i0 + r) * EMB + t0 + c];
        }
        idx = threadIdx.x;
#pragma unroll
        for (int rep = 0; rep < 4; rep++, idx += 256) {
            int r = idx >> 6, c = idx & 63;
            Bs[r][c] = W1[(size_t)(t0 + r) * EMB + e0 + c];
        }
        __syncthreads();
#pragma unroll
        for (int t = 0; t < 16; t++) {
            float a[4], b[4];
#pragma unroll
            for (int u = 0; u < 4; u++) { a[u] = As[ty * 4 + u][t]; b[u] = Bs[t][tx * 4 + u]; }
#pragma unroll
            for (int i = 0; i < 4; i++)
#pragma unroll
                for (int j = 0; j < 4; j++) acc[i][j] += a[i] * b[j];
        }
    }
#pragma unroll
    for (int i = 0; i < 4; i++)
#pragma unroll
        for (int j = 0; j < 4; j++)
            g_Wc[(size_t)(i0 + ty * 4 + i) * EMB + e0 + tx * 4 + j] = acc[i][j];
}

// ---------------- 1b) bc = W2 @ b1 + b2; split Wc ----------------
__global__ void k_bc(const float* __restrict__ W2, const float* __restrict__ b1,
                     const float* __restrict__ b2) {
    int i = blockIdx.x * blockDim.x + threadIdx.x;
    if (i < EMB) {
        float s = 0.f;
        for (int j = 0; j < EMB; j++) s += W2[(size_t)i * EMB + j] * b1[j];
        g_bc[i] = s + b2[i];
    }
}

__global__ void k_wcsplit() {
    int i = blockIdx.x * 256 + threadIdx.x;
    if (i < EMB * EMB) {
        float x = g_Wc[i];
        __nv_bfloat16 h = __float2bfloat16(x);
        g_WcHi[i] = h;
        g_WcLo[i] = __float2bfloat16(x - __bfloat162float(h));
    }
}

// ---------------- 2) attend: cp.async 4-stage + wmma ----------------
// per-stage byte offsets (X tiles [32][136] bf16, Wa tiles [128][40] bf16)
#define OF_X1H  0
#define OF_X1L  8704
#define OF_X2H  17408
#define OF_X2L  26112
#define OF_WAH  34816
#define OF_WAL  45056
#define STG     55296
// tail after 4 stages
#define OF_VA    221184
#define OF_SPART 221696
#define OF_SC    223744
#define OF_BETA  224256
#define OF_RED   224768
#define SMEM_DYN 224784

typedef wmma::fragment<wmma::matrix_a, 16, 16, 16, __nv_bfloat16, wmma::row_major> FragA;
typedef wmma::fragment<wmma::matrix_b, 16, 16, 16, __nv_bfloat16, wmma::row_major> FragB;
typedef wmma::fragment<wmma::accumulator, 16, 16, 16, float> FragC;

// issue all cp.async for chunk cg (each thread issues 4 or 6 x 16B)
__device__ __forceinline__ void issue_chunk(uint32_t sb32, int cg, int tid, int m) {
    uint32_t base = sb32 + (uint32_t)(cg & 3) * STG;
    bool phA = (cg < 24);
    int e0  = (phA ? cg : cg - 24) * 32;
    int wa0 = phA ? e0 : (EMB + e0);

    // Wa hi/lo tiles: 128 rows x 4 chunks
    {
        int row = tid >> 2, c = tid & 3;
        size_t go = (size_t)row * (2 * EMB) + wa0 + c * 8;
        uint32_t so = base + row * 80 + c * 16;
        cp16(so + OF_WAH, g_WaHi + go);
        cp16(so + OF_WAL, g_WaLo + go);
    }
    // X tiles: 32 rows x 16 chunks
    {
        int row = tid >> 4, c = tid & 15;
        uint32_t so = base + row * 272 + c * 16;
        size_t r1 = (size_t)m * XROWS + (phA ? e0 : (EMB + e0)) + row;
        size_t g1 = r1 * NN + c * 8;
        cp16(so + OF_X1H, g_XHi + g1);
        cp16(so + OF_X1L, g_XLo + g1);
        if (!phA) {
            size_t g2 = ((size_t)m * XROWS + 2 * EMB + 1 + e0 + row) * NN + c * 8;
            cp16(so + OF_X2H, g_XHi + g2);
            cp16(so + OF_X2L, g_XLo + g2);
        }
    }
}

template <int NP>
__device__ __forceinline__ void mma_chunk(FragC (&acc)[2][2][2], const char* base,
                                          int wk, int wn) {
    const __nv_bfloat16* wah = (const __nv_bfloat16*)(base + OF_WAH);
    const __nv_bfloat16* wal = (const __nv_bfloat16*)(base + OF_WAL);
#pragma unroll
    for (int ks = 0; ks < 2; ks++) {
        int ek = ks * 16;
        FragA aH[2], aL[2];
#pragma unroll
        for (int f = 0; f < 2; f++) {
            wmma::load_matrix_sync(aH[f], wah + (wk * 32 + f * 16) * 40 + ek, 40);
            wmma::load_matrix_sync(aL[f], wal + (wk * 32 + f * 16) * 40 + ek, 40);
        }
#pragma unroll
        for (int p = 0; p < NP; p++) {
            const __nv_bfloat16* xh = (const __nv_bfloat16*)(base + (p ? OF_X2H : OF_X1H));
            const __nv_bfloat16* xl = (const __nv_bfloat16*)(base + (p ? OF_X2L : OF_X1L));
#pragma unroll
            for (int fn = 0; fn < 2; fn++) {
                FragB bH, bL;
                wmma::load_matrix_sync(bH, xh + ek * 136 + wn * 32 + fn * 16, 136);
                wmma::load_matrix_sync(bL, xl + ek * 136 + wn * 32 + fn * 16, 136);
#pragma unroll
                for (int fk = 0; fk < 2; fk++) {
                    wmma::mma_sync(acc[p][fk][fn], aH[fk], bH, acc[p][fk][fn]);
                    wmma::mma_sync(acc[p][fk][fn], aH[fk], bL, acc[p][fk][fn]);
                    wmma::mma_sync(acc[p][fk][fn], aL[fk], bH, acc[p][fk][fn]);
                }
            }
        }
    }
}

__global__ __launch_bounds__(512, 1)
void k_attend(const float* __restrict__ X, const float* __restrict__ va) {
    extern __shared__ __align__(16) char sb[];
    uint32_t sb32 = cvta_smem(sb);

    int m    = blockIdx.x;
    int tid  = threadIdx.x;
    int wid  = tid >> 5, lane = tid & 31;
    int wk   = wid & 3, wn = wid >> 2;
    const float* Xm = X + (size_t)m * XROWS * NN;

    float* vas   = (float*)(sb + OF_VA);
    float* spart = (float*)(sb + OF_SPART);
    float* scs   = (float*)(sb + OF_SC);
    float* beta  = (float*)(sb + OF_BETA);
    float* red   = (float*)(sb + OF_RED);

    if (tid < 128) vas[tid] = va[tid];

    FragC acc[2][2][2];
#pragma unroll
    for (int fk = 0; fk < 2; fk++)
#pragma unroll
        for (int fn = 0; fn < 2; fn++) wmma::fill_fragment(acc[0][fk][fn], 0.f);

    // prologue: 3 chunks in flight
    issue_chunk(sb32, 0, tid, m); cp_commit();
    issue_chunk(sb32, 1, tid, m); cp_commit();
    issue_chunk(sb32, 2, tid, m); cp_commit();

    // ---- main loop: 24 hq chunks + 24 dual-pool chunks ----
#pragma unroll 1
    for (int cg = 0; cg < 48; cg++) {
        cp_wait2();
        __syncthreads();
        if (cg == 24) {
            // acc1 = copy(hq)
#pragma unroll
            for (int fk = 0; fk < 2; fk++)
#pragma unroll
                for (int fn = 0; fn < 2; fn++)
#pragma unroll
                    for (int i = 0; i < acc[0][fk][fn].num_elements; i++)
                        acc[1][fk][fn].x[i] = acc[0][fk][fn].x[i];
        }
        if (cg + 3 < 48) issue_chunk(sb32, cg + 3, tid, m);
        cp_commit();
        const char* base = sb + (size_t)(cg & 3) * STG;
        if (cg < 24) mma_chunk<1>(acc, base, wk, wn);
        else         mma_chunk<2>(acc, base, wk, wn);
    }
    __syncthreads();

    // ---- per-pool: score -> softmax -> pooling ----
    float* scr = (float*)sb + wid * 320;   // reuse stage smem (16x20 per warp)
#pragma unroll 1
    for (int p = 0; p < 2; p++) {
        const int exp0 = (p == 0) ? EMB : (2 * EMB + 1);
        const int ev   = (p == 0) ? (2 * EMB) : (3 * EMB + 1);

        int j = lane & 15, rh = (lane >> 4) * 8;
#pragma unroll
        for (int fn = 0; fn < 2; fn++) {
            float ps = 0.f;
#pragma unroll
            for (int fk = 0; fk < 2; fk++) {
                wmma::store_matrix_sync(scr, acc[p][fk][fn], 20, wmma::mem_row_major);
                __syncwarp();
#pragma unroll
                for (int r = 0; r < 8; r++) {
                    int k = wk * 32 + fk * 16 + rh + r;
                    ps += vas[k] * tanh_fast(scr[(rh + r) * 20 + j]);
                }
                __syncwarp();
            }
            ps += __shfl_xor_sync(0xffffffffu, ps, 16);
            if (lane < 16)
                spart[wk * 128 + wn * 32 + fn * 16 + lane] = ps;
        }
        __syncthreads();

        if (tid < 128) {
            float sc = spart[tid] + spart[128 + tid] + spart[256 + tid] + spart[384 + tid];
            scs[tid] = sc * Xm[(size_t)ev * NN + tid];
        }
        __syncthreads();
        if (tid < 32) {
            float mx = fmaxf(fmaxf(scs[tid], scs[tid + 32]),
                             fmaxf(scs[tid + 64], scs[tid + 96]));
#pragma unroll
            for (int off = 16; off; off >>= 1)
                mx = fmaxf(mx, __shfl_xor_sync(0xffffffffu, mx, off));
            if (tid == 0) red[0] = mx;
        }
        __syncthreads();
        float mx = red[0];
        if (tid < 128) beta[tid] = expf(scs[tid] - mx);
        __syncthreads();
        if (tid < 32) {
            float s = beta[tid] + beta[tid + 32] + beta[tid + 64] + beta[tid + 96];
#pragma unroll
            for (int off = 16; off; off >>= 1)
                s += __shfl_xor_sync(0xffffffffu, s, off);
            if (tid == 0) red[0] = s;
        }
        __syncthreads();
        float inv = 1.f / red[0];
        if (tid < 128) beta[tid] *= inv;
        __syncthreads();

        // pooling: p[e] = sum_n beta[n] * Xp[e][n]  (fp32 X, exact)
        for (int e = wid; e < EMB; e += 16) {
            const float* row = Xm + (size_t)(exp0 + e) * NN;
            float s = row[lane]      * beta[lane]      +
                      row[lane + 32] * beta[lane + 32] +
                      row[lane + 64] * beta[lane + 64] +
                      row[lane + 96] * beta[lane + 96];
#pragma unroll
            for (int off = 16; off; off >>= 1)
                s += __shfl_xor_sync(0xffffffffu, s, off);
            if (lane == 0) {
                size_t o = ((size_t)m * 3 + p) * EMB + e;
                __nv_bfloat16 h = __float2bfloat16(s);
                g_PHi[o] = h;
                g_PLo[o] = __float2bfloat16(s - __bfloat162float(h));
            }
        }
        __syncthreads();
    }

    // qv[e] = Xq[e][0]
    for (int e = tid; e < EMB; e += 512) {
        float s = Xm[(size_t)e * NN];
        size_t o = ((size_t)m * 3 + 2) * EMB + e;
        __nv_bfloat16 h = __float2bfloat16(s);
        g_PHi[o] = h;
        g_PLo[o] = __float2bfloat16(s - __bfloat162float(h));
    }
}

// ---------------- 3) MLP: Z = relu(P @ Wc^T + bc), wmma ----------------
typedef wmma::fragment<wmma::matrix_b, 16, 16, 16, __nv_bfloat16, wmma::col_major> FragBc;

__global__ __launch_bounds__(256) void k_mlp() {
    __shared__ __nv_bfloat16 Ah[128][40], Al[128][40];
    __shared__ __nv_bfloat16 Bh[128][40], Bl[128][40];
    int r0 = blockIdx.x * 128, i0 = blockIdx.y * 128;
    int tid = threadIdx.x;
    int wid = tid >> 5, lane = tid & 31;
    int wm = wid & 1, wn = wid >> 1;

    FragC acc[4][2];
#pragma unroll
    for (int i = 0; i < 4; i++)
#pragma unroll
        for (int j = 0; j < 2; j++) wmma::fill_fragment(acc[i][j], 0.f);

#pragma unroll 1
    for (int e0 = 0; e0 < EMB; e0 += 32) {
        __syncthreads();
#pragma unroll
        for (int k = 0; k < 4; k++) {
            int l = tid + k * 256;
            int row = l >> 3, c = l & 7;
            *(uint2*)&Ah[row][c * 4] = *((const uint2*)(g_PHi + (size_t)(r0 + row) * EMB + e0) + c);
            *(uint2*)&Al[row][c * 4] = *((const uint2*)(g_PLo + (size_t)(r0 + row) * EMB + e0) + c);
            *(uint2*)&Bh[row][c * 4] = *((const uint2*)(g_WcHi + (size_t)(i0 + row) * EMB + e0) + c);
            *(uint2*)&Bl[row][c * 4] = *((const uint2*)(g_WcLo + (size_t)(i0 + row) * EMB + e0) + c);
        }
        __syncthreads();
#pragma unroll
        for (int ks = 0; ks < 2; ks++) {
            int ek = ks * 16;
            FragBc bh[2], bl[2];
#pragma unroll
            for (int fn = 0; fn < 2; fn++) {
                wmma::load_matrix_sync(bh[fn], &Bh[wn * 32 + fn * 16][ek], 40);
                wmma::load_matrix_sync(bl[fn], &Bl[wn * 32 + fn * 16][ek], 40);
            }
#pragma unroll
            for (int fm = 0; fm < 4; fm++) {
                FragA ah, al;
                wmma::load_matrix_sync(ah, &Ah[wm * 64 + fm * 16][ek], 40);
                wmma::load_matrix_sync(al, &Al[wm * 64 + fm * 16][ek], 40);
#pragma unroll
                for (int fn = 0; fn < 2; fn++) {
                    wmma::mma_sync(acc[fm][fn], ah, bh[fn], acc[fm][fn]);
                    wmma::mma_sync(acc[fm][fn], ah, bl[fn], acc[fm][fn]);
                    wmma::mma_sync(acc[fm][fn], al, bh[fn], acc[fm][fn]);
                }
            }
        }
    }
    __syncthreads();

    float* scr = (float*)&Ah[0][0] + wid * 320;
#pragma unroll
    for (int fm = 0; fm < 4; fm++)
#pragma unroll
        for (int fn = 0; fn < 2; fn++) {
            wmma::store_matrix_sync(scr, acc[fm][fn], 20, wmma::mem_row_major);
            __syncwarp();
#pragma unroll
            for (int u = 0; u < 8; u++) {
                int el = lane + u * 32;
                int r = el >> 4, c = el & 15;
                int gi = i0 + wn * 32 + fn * 16 + c;
                int gr = r0 + wm * 64 + fm * 16 + r;
                g_Z[(size_t)gr * EMB + gi] = fmaxf(scr[r * 20 + c] + g_bc[gi], 0.f);
            }
            __syncwarp();
        }
}

// ---------------- 4) final head ----------------
__global__ void k_final(const float* __restrict__ W3, const float* __restrict__ b3,
                        float* __restrict__ out) {
    __shared__ float red[8];
    int m = blockIdx.x;
    const float* z1 = g_Z + (size_t)m * 3 * EMB;
    const float* z2 = z1 + EMB;
    const float* zq = z1 + 2 * EMB;
    float s = 0.f;
    for (int i = threadIdx.x; i < EMB; i += 256) {
        float a = z1[i], b = z2[i], q = zq[i];
        s += W3[i] * a + W3[EMB + i] * b +
             W3[2 * EMB + i] * fabsf(a - b) +
             W3[3 * EMB + i] * fabsf(a - q) +
             W3[4 * EMB + i] * fabsf(b - q);
    }
#pragma unroll
    for (int off = 16; off; off >>= 1)
        s += __shfl_xor_sync(0xffffffffu, s, off);
    if ((threadIdx.x & 31) == 0) red[threadIdx.x >> 5] = s;
    __syncthreads();
    if (threadIdx.x == 0) {
        float t = 0.f;
#pragma unroll
        for (int w = 0; w < 8; w++) t += red[w];
        out[m] = fmaxf(t + b3[0], 0.f);
    }
}

// ---------------- launch ----------------
extern "C" void kernel_launch(void* const* d_in, const int* in_sizes, int n_in,
                              void* d_out, int out_size) {
    (void)in_sizes; (void)n_in; (void)out_size;
    const float* X  = (const float*)d_in[0];
    const float* Wa = (const float*)d_in[1];
    const float* va = (const float*)d_in[2];
    const float* W1 = (const float*)d_in[3];
    const float* b1 = (const float*)d_in[4];
    const float* W2 = (const float*)d_in[5];
    const float* b2 = (const float*)d_in[6];
    const float* W3 = (const float*)d_in[7];
    const float* b3 = (const float*)d_in[8];
    float* out = (float*)d_out;

    static int smem_set = 0;
    if (!smem_set) {
        cudaFuncSetAttribute(k_attend, cudaFuncAttributeMaxDynamicSharedMemorySize,
                             SMEM_DYN);
        smem_set = 1;
    }

    k_split<<<768, 256>>>(Wa);
    k_xsplit<<<4736, 256>>>((const float4*)X);
    k_wc<<<dim3(12, 12), 256>>>(W1, W2);
    k_bc<<<6, 128>>>(W2, b1, b2);
    k_wcsplit<<<(EMB * EMB + 255) / 256, 256>>>();
    k_attend<<<MROWS, 512, SMEM_DYN>>>(X, va);
    k_mlp<<<dim3(24, 6), 256>>>();
    k_final<<<MROWS, 256>>>(W3, b3, out);
}

// round 11
// speedup vs baseline: 1.2226x; 1.2226x over previous
#include <cuda_runtime.h>
#include <cuda_bf16.h>
#include <mma.h>
#include <math.h>
#include <stdint.h>

using namespace nvcuda;

#define EMB   768
#define MROWS 1024
#define NN    128
#define KK    128
#define XROWS (3*EMB+2)   // 2306

// ---------------- device scratch ----------------
__device__ __nv_bfloat16 g_WaHi[KK * 2 * EMB];   // [k][e] row-major
__device__ __nv_bfloat16 g_WaLo[KK * 2 * EMB];
__device__ float g_Wc [EMB * EMB];
__device__ __nv_bfloat16 g_WcHi[EMB * EMB];
__device__ __nv_bfloat16 g_WcLo[EMB * EMB];
__device__ float g_bc [EMB];
__device__ __nv_bfloat16 g_PHi[(size_t)MROWS * 3 * EMB];
__device__ __nv_bfloat16 g_PLo[(size_t)MROWS * 3 * EMB];
__device__ float g_Z  [(size_t)MROWS * 3 * EMB];

// ---------------- helpers ----------------
__device__ __forceinline__ uint32_t cvta_smem(const void* p) {
    uint32_t a;
    asm("{ .reg .u64 t; cvta.to.shared.u64 t, %1; cvt.u32.u64 %0, t; }" : "=r"(a) : "l"(p));
    return a;
}
__device__ __forceinline__ float tanh_fast(float x) {
    float y;
    asm("tanh.approx.f32 %0, %1;" : "=f"(y) : "f"(x));
    return y;
}
__device__ __forceinline__ void cp16(uint32_t dst, const void* src) {
    asm volatile("cp.async.cg.shared.global [%0], [%1], 16;" :: "r"(dst), "l"(src) : "memory");
}
__device__ __forceinline__ void cp_commit() {
    asm volatile("cp.async.commit_group;" ::: "memory");
}
__device__ __forceinline__ void cp_wait1() {
    asm volatile("cp.async.wait_group 1;" ::: "memory");
}

// ---------------- 0) split Wa ----------------
__global__ void k_split(const float* __restrict__ Wa) {
    int i = blockIdx.x * 256 + threadIdx.x;
    if (i < KK * 2 * EMB) {
        float x = Wa[i];
        __nv_bfloat16 h = __float2bfloat16(x);
        g_WaHi[i] = h;
        g_WaLo[i] = __float2bfloat16(x - __bfloat162float(h));
    }
}

// ---------------- 1) Wc = W2 @ W1 ----------------
__global__ void k_wc(const float* __restrict__ W1, const float* __restrict__ W2) {
    __shared__ float As[64][17];
    __shared__ float Bs[16][65];
    int i0 = blockIdx.y * 64, e0 = blockIdx.x * 64;
    int tx = threadIdx.x & 15, ty = threadIdx.x >> 4;
    float acc[4][4];
#pragma unroll
    for (int i = 0; i < 4; i++)
#pragma unroll
        for (int j = 0; j < 4; j++) acc[i][j] = 0.f;

    for (int t0 = 0; t0 < EMB; t0 += 16) {
        __syncthreads();
        int idx = threadIdx.x;
#pragma unroll
        for (int rep = 0; rep < 4; rep++, idx += 256) {
            int r = idx >> 4, c = idx & 15;
            As[r][c] = W2[(size_t)(i0 + r) * EMB + t0 + c];
        }
        idx = threadIdx.x;
#pragma unroll
        for (int rep = 0; rep < 4; rep++, idx += 256) {
            int r = idx >> 6, c = idx & 63;
            Bs[r][c] = W1[(size_t)(t0 + r) * EMB + e0 + c];
        }
        __syncthreads();
#pragma unroll
        for (int t = 0; t < 16; t++) {
            float a[4], b[4];
#pragma unroll
            for (int u = 0; u < 4; u++) { a[u] = As[ty * 4 + u][t]; b[u] = Bs[t][tx * 4 + u]; }
#pragma unroll
            for (int i = 0; i < 4; i++)
#pragma unroll
                for (int j = 0; j < 4; j++) acc[i][j] += a[i] * b[j];
        }
    }
#pragma unroll
    for (int i = 0; i < 4; i++)
#pragma unroll
        for (int j = 0; j < 4; j++)
            g_Wc[(size_t)(i0 + ty * 4 + i) * EMB + e0 + tx * 4 + j] = acc[i][j];
}

// ---------------- 1b) bc = W2 @ b1 + b2 (warp per row) ----------------
__global__ void k_bc(const float* __restrict__ W2, const float* __restrict__ b1,
                     const float* __restrict__ b2) {
    int gw = (blockIdx.x * blockDim.x + threadIdx.x) >> 5;
    int lane = threadIdx.x & 31;
    if (gw < EMB) {
        float s = 0.f;
        for (int j = lane; j < EMB; j += 32) s += W2[(size_t)gw * EMB + j] * b1[j];
#pragma unroll
        for (int off = 16; off; off >>= 1)
            s += __shfl_xor_sync(0xffffffffu, s, off);
        if (lane == 0) g_bc[gw] = s + b2[gw];
    }
}

__global__ void k_wcsplit() {
    int i = blockIdx.x * 256 + threadIdx.x;
    if (i < EMB * EMB) {
        float x = g_Wc[i];
        __nv_bfloat16 h = __float2bfloat16(x);
        g_WcHi[i] = h;
        g_WcLo[i] = __float2bfloat16(x - __bfloat162float(h));
    }
}

// ---------------- 2) attend: cp.async rings + wmma ----------------
// smem layout (byte offsets in dynamic smem):
//  XRING: 2 stages x (2 pools x [32][128] fp32 16KB) = 65536
//  WRING: 3 stages x (hi [128][32] 8KB + lo 8KB)     = 49152
//  XTILE: 2 bufs x (2 pools x (hi [32][136] 8704 + lo 8704)) = 69632
#define XRING  0
#define XSTG   32768
#define WRING  65536
#define WSTG   16384
#define XTILE  114688
#define XBUF   34816
// tail
#define OF_VA    184320
#define OF_SPART 184832
#define OF_SC    186880
#define OF_BETA  187392
#define OF_RED   187904
#define SMEM_DYN 187920

typedef wmma::fragment<wmma::matrix_a, 16, 16, 16, __nv_bfloat16, wmma::row_major> FragA;
typedef wmma::fragment<wmma::matrix_b, 16, 16, 16, __nv_bfloat16, wmma::row_major> FragB;
typedef wmma::fragment<wmma::accumulator, 16, 16, 16, float> FragC;

// issue cp.async for chunk cg: Wa (bf16, direct) + X (fp32 staging)
__device__ __forceinline__ void issue_chunk(uint32_t sb32, int cg, int tid,
                                            const float* __restrict__ Xm) {
    bool phA = (cg < 24);
    int e0  = (phA ? cg : cg - 24) * 32;
    int wa0 = phA ? e0 : (EMB + e0);

    // Wa hi/lo [128][32]: 128 rows x 4 x 16B
    {
        uint32_t wbase = sb32 + WRING + (uint32_t)(cg % 3) * WSTG;
        int row = tid >> 2, c = tid & 3;
        size_t go = (size_t)row * (2 * EMB) + wa0 + c * 8;
        uint32_t so = wbase + row * 64 + c * 16;
        cp16(so, g_WaHi + go);
        cp16(so + 8192, g_WaLo + go);
    }
    // X fp32 [32][128]: 512 B/row -> 32 rows x 32 x 16B = 1024 chunks (2 per thread)
    {
        uint32_t xbase = sb32 + XRING + (uint32_t)(cg & 1) * XSTG;
#pragma unroll
        for (int r = 0; r < 2; r++) {
            int l = tid + r * 512;
            int row = l >> 5, c = l & 31;
            uint32_t so = xbase + row * 512 + c * 16;
            int er1 = (phA ? e0 : (EMB + e0)) + row;
            cp16(so, Xm + (size_t)er1 * NN + c * 4);
            if (!phA) {
                int er2 = 2 * EMB + 1 + e0 + row;
                cp16(so + 16384, Xm + (size_t)er2 * NN + c * 4);
            }
        }
    }
}

// convert fp32 stage -> bf16 hi/lo tiles
__device__ __forceinline__ void cvt_chunk(char* sb, int cg, int tid) {
    bool phA = (cg < 24);
    const char* xs = sb + XRING + (size_t)(cg & 1) * XSTG;
    char* xt = sb + XTILE + (size_t)(cg & 1) * XBUF;
    int np = phA ? 1 : 2;
#pragma unroll 2
    for (int p = 0; p < np; p++) {
        const float4* src = (const float4*)(xs + p * 16384);
        __nv_bfloat16* dh = (__nv_bfloat16*)(xt + p * 17408);
        __nv_bfloat16* dl = dh + 4352;   // +8704 bytes
#pragma unroll
        for (int r = 0; r < 2; r++) {
            int l = tid + r * 512;          // 1024 float4
            int row = l >> 5, c4 = l & 31;
            float4 v = src[l];
            __nv_bfloat16 hx = __float2bfloat16(v.x);
            __nv_bfloat16 hy = __float2bfloat16(v.y);
            __nv_bfloat16 hz = __float2bfloat16(v.z);
            __nv_bfloat16 hw = __float2bfloat16(v.w);
            __nv_bfloat162 hA(hx, hy), hB(hz, hw);
            __nv_bfloat162 lA(__float2bfloat16(v.x - __bfloat162float(hx)),
                              __float2bfloat16(v.y - __bfloat162float(hy)));
            __nv_bfloat162 lB(__float2bfloat16(v.z - __bfloat162float(hz)),
                              __float2bfloat16(v.w - __bfloat162float(hw)));
            __nv_bfloat162* ph = (__nv_bfloat162*)(dh + row * 136 + c4 * 4);
            __nv_bfloat162* pl = (__nv_bfloat162*)(dl + row * 136 + c4 * 4);
            ph[0] = hA; ph[1] = hB;
            pl[0] = lA; pl[1] = lB;
        }
    }
}

template <int NP>
__device__ __forceinline__ void mma_chunk(FragC (&acc)[2][2][2], const char* sb,
                                          int cg, int wk, int wn) {
    const __nv_bfloat16* wah = (const __nv_bfloat16*)(sb + WRING + (size_t)(cg % 3) * WSTG);
    const __nv_bfloat16* wal = wah + 4096;   // +8192 bytes
    const char* xt = sb + XTILE + (size_t)(cg & 1) * XBUF;
#pragma unroll
    for (int ks = 0; ks < 2; ks++) {
        int ek = ks * 16;
        FragA aH[2], aL[2];
#pragma unroll
        for (int f = 0; f < 2; f++) {
            wmma::load_matrix_sync(aH[f], wah + (wk * 32 + f * 16) * 32 + ek, 32);
            wmma::load_matrix_sync(aL[f], wal + (wk * 32 + f * 16) * 32 + ek, 32);
        }
#pragma unroll
        for (int p = 0; p < NP; p++) {
            const __nv_bfloat16* xh = (const __nv_bfloat16*)(xt + p * 17408);
            const __nv_bfloat16* xl = xh + 4352;
#pragma unroll
            for (int fn = 0; fn < 2; fn++) {
                FragB bH, bL;
                wmma::load_matrix_sync(bH, xh + ek * 136 + wn * 32 + fn * 16, 136);
                wmma::load_matrix_sync(bL, xl + ek * 136 + wn * 32 + fn * 16, 136);
#pragma unroll
                for (int fk = 0; fk < 2; fk++) {
                    wmma::mma_sync(acc[p][fk][fn], aH[fk], bH, acc[p][fk][fn]);
                    wmma::mma_sync(acc[p][fk][fn], aH[fk], bL, acc[p][fk][fn]);
                    wmma::mma_sync(acc[p][fk][fn], aL[fk], bH, acc[p][fk][fn]);
                }
            }
        }
    }
}

__global__ __launch_bounds__(512, 1)
void k_attend(const float* __restrict__ X, const float* __restrict__ va) {
    extern __shared__ __align__(16) char sb[];
    uint32_t sb32 = cvta_smem(sb);

    int m    = blockIdx.x;
    int tid  = threadIdx.x;
    int wid  = tid >> 5, lane = tid & 31;
    int wk   = wid & 3, wn = wid >> 2;
    const float* Xm = X + (size_t)m * XROWS * NN;

    float* vas   = (float*)(sb + OF_VA);
    float* spart = (float*)(sb + OF_SPART);
    float* scs   = (float*)(sb + OF_SC);
    float* beta  = (float*)(sb + OF_BETA);
    float* red   = (float*)(sb + OF_RED);

    if (tid < 128) vas[tid] = va[tid];

    FragC acc[2][2][2];
#pragma unroll
    for (int fk = 0; fk < 2; fk++)
#pragma unroll
        for (int fn = 0; fn < 2; fn++) wmma::fill_fragment(acc[0][fk][fn], 0.f);

    // prologue: 2 chunks in flight
    issue_chunk(sb32, 0, tid, Xm); cp_commit();
    issue_chunk(sb32, 1, tid, Xm); cp_commit();

    // ---- main loop: 24 hq chunks + 24 dual-pool chunks ----
#pragma unroll 1
    for (int cg = 0; cg < 48; cg++) {
        cp_wait1();                    // chunk cg has landed
        cvt_chunk(sb, cg, tid);        // fp32 stage -> bf16 tiles (buf cg&1)
        __syncthreads();               // tiles complete; prev MMA done
        if (cg == 24) {
            // acc1 = copy(hq)
#pragma unroll
            for (int fk = 0; fk < 2; fk++)
#pragma unroll
                for (int fn = 0; fn < 2; fn++)
#pragma unroll
                    for (int i = 0; i < acc[0][fk][fn].num_elements; i++)
                        acc[1][fk][fn].x[i] = acc[0][fk][fn].x[i];
        }
        if (cg + 2 < 48) issue_chunk(sb32, cg + 2, tid, Xm);
        cp_commit();
        if (cg < 24) mma_chunk<1>(acc, sb, cg, wk, wn);
        else         mma_chunk<2>(acc, sb, cg, wk, wn);
    }
    __syncthreads();

    // ---- per-pool: score -> softmax -> pooling ----
    float* scr = (float*)sb + wid * 320;   // reuse ring smem (16x20 per warp)
#pragma unroll 1
    for (int p = 0; p < 2; p++) {
        const int exp0 = (p == 0) ? EMB : (2 * EMB + 1);
        const int ev   = (p == 0) ? (2 * EMB) : (3 * EMB + 1);

        int j = lane & 15, rh = (lane >> 4) * 8;
#pragma unroll
        for (int fn = 0; fn < 2; fn++) {
            float ps = 0.f;
#pragma unroll
            for (int fk = 0; fk < 2; fk++) {
                wmma::store_matrix_sync(scr, acc[p][fk][fn], 20, wmma::mem_row_major);
                __syncwarp();
#pragma unroll
                for (int r = 0; r < 8; r++) {
                    int k = wk * 32 + fk * 16 + rh + r;
                    ps += vas[k] * tanh_fast(scr[(rh + r) * 20 + j]);
                }
                __syncwarp();
            }
            ps += __shfl_xor_sync(0xffffffffu, ps, 16);
            if (lane < 16)
                spart[wk * 128 + wn * 32 + fn * 16 + lane] = ps;
        }
        __syncthreads();

        if (tid < 128) {
            float sc = spart[tid] + spart[128 + tid] + spart[256 + tid] + spart[384 + tid];
            scs[tid] = sc * Xm[(size_t)ev * NN + tid];
        }
        __syncthreads();
        if (tid < 32) {
            float mx = fmaxf(fmaxf(scs[tid], scs[tid + 32]),
                             fmaxf(scs[tid + 64], scs[tid + 96]));
#pragma unroll
            for (int off = 16; off; off >>= 1)
                mx = fmaxf(mx, __shfl_xor_sync(0xffffffffu, mx, off));
            if (tid == 0) red[0] = mx;
        }
        __syncthreads();
        float mx = red[0];
        if (tid < 128) beta[tid] = expf(scs[tid] - mx);
        __syncthreads();
        if (tid < 32) {
            float s = beta[tid] + beta[tid + 32] + beta[tid + 64] + beta[tid + 96];
#pragma unroll
            for (int off = 16; off; off >>= 1)
                s += __shfl_xor_sync(0xffffffffu, s, off);
            if (tid == 0) red[0] = s;
        }
        __syncthreads();
        float inv = 1.f / red[0];
        if (tid < 128) beta[tid] *= inv;
        __syncthreads();

        // pooling: p[e] = sum_n beta[n] * Xp[e][n]; unrolled x3
        float b0 = beta[lane], b1v = beta[lane + 32], b2v = beta[lane + 64], b3v = beta[lane + 96];
#pragma unroll 1
        for (int e = wid; e < EMB; e += 48) {
            const float* r0 = Xm + (size_t)(exp0 + e) * NN;
            const float* r1 = r0 + (size_t)16 * NN;
            const float* r2 = r0 + (size_t)32 * NN;
            float x0a = r0[lane], x0b = r0[lane + 32], x0c = r0[lane + 64], x0d = r0[lane + 96];
            float x1a = r1[lane], x1b = r1[lane + 32], x1c = r1[lane + 64], x1d = r1[lane + 96];
            float x2a = r2[lane], x2b = r2[lane + 32], x2c = r2[lane + 64], x2d = r2[lane + 96];
            float s0 = x0a * b0 + x0b * b1v + x0c * b2v + x0d * b3v;
            float s1 = x1a * b0 + x1b * b1v + x1c * b2v + x1d * b3v;
            float s2 = x2a * b0 + x2b * b1v + x2c * b2v + x2d * b3v;
#pragma unroll
            for (int off = 16; off; off >>= 1) {
                s0 += __shfl_xor_sync(0xffffffffu, s0, off);
                s1 += __shfl_xor_sync(0xffffffffu, s1, off);
                s2 += __shfl_xor_sync(0xffffffffu, s2, off);
            }
            if (lane == 0) {
                size_t o = ((size_t)m * 3 + p) * EMB + e;
                float sv[3] = {s0, s1, s2};
#pragma unroll
                for (int u = 0; u < 3; u++) {
                    __nv_bfloat16 h = __float2bfloat16(sv[u]);
                    g_PHi[o + u * 16] = h;
                    g_PLo[o + u * 16] = __float2bfloat16(sv[u] - __bfloat162float(h));
                }
            }
        }
        __syncthreads();
    }

    // qv[e] = Xq[e][0]
    for (int e = tid; e < EMB; e += 512) {
        float s = Xm[(size_t)e * NN];
        size_t o = ((size_t)m * 3 + 2) * EMB + e;
        __nv_bfloat16 h = __float2bfloat16(s);
        g_PHi[o] = h;
        g_PLo[o] = __float2bfloat16(s - __bfloat162float(h));
    }
}

// ---------------- 3) MLP: Z = relu(P @ Wc^T + bc), wmma ----------------
typedef wmma::fragment<wmma::matrix_b, 16, 16, 16, __nv_bfloat16, wmma::col_major> FragBc;

__global__ __launch_bounds__(256) void k_mlp() {
    __shared__ __nv_bfloat16 Ah[128][48], Al[128][48];   // stride 48 el = 96B (ldsm-legal)
    __shared__ __nv_bfloat16 Bh[128][48], Bl[128][48];
    int r0 = blockIdx.x * 128, i0 = blockIdx.y * 128;
    int tid = threadIdx.x;
    int wid = tid >> 5, lane = tid & 31;
    int wm = wid & 1, wn = wid >> 1;

    FragC acc[4][2];
#pragma unroll
    for (int i = 0; i < 4; i++)
#pragma unroll
        for (int j = 0; j < 2; j++) wmma::fill_fragment(acc[i][j], 0.f);

#pragma unroll 1
    for (int e0 = 0; e0 < EMB; e0 += 32) {
        __syncthreads();
#pragma unroll
        for (int k = 0; k < 4; k++) {
            int l = tid + k * 256;
            int row = l >> 3, c = l & 7;
            *(uint2*)&Ah[row][c * 4] = *((const uint2*)(g_PHi + (size_t)(r0 + row) * EMB + e0) + c);
            *(uint2*)&Al[row][c * 4] = *((const uint2*)(g_PLo + (size_t)(r0 + row) * EMB + e0) + c);
            *(uint2*)&Bh[row][c * 4] = *((const uint2*)(g_WcHi + (size_t)(i0 + row) * EMB + e0) + c);
            *(uint2*)&Bl[row][c * 4] = *((const uint2*)(g_WcLo + (size_t)(i0 + row) * EMB + e0) + c);
        }
        __syncthreads();
#pragma unroll
        for (int ks = 0; ks < 2; ks++) {
            int ek = ks * 16;
            FragBc bh[2], bl[2];
#pragma unroll
            for (int fn = 0; fn < 2; fn++) {
                wmma::load_matrix_sync(bh[fn], &Bh[wn * 32 + fn * 16][ek], 48);
                wmma::load_matrix_sync(bl[fn], &Bl[wn * 32 + fn * 16][ek], 48);
            }
#pragma unroll
            for (int fm = 0; fm < 4; fm++) {
                FragA ah, al;
                wmma::load_matrix_sync(ah, &Ah[wm * 64 + fm * 16][ek], 48);
                wmma::load_matrix_sync(al, &Al[wm * 64 + fm * 16][ek], 48);
#pragma unroll
                for (int fn = 0; fn < 2; fn++) {
                    wmma::mma_sync(acc[fm][fn], ah, bh[fn], acc[fm][fn]);
                    wmma::mma_sync(acc[fm][fn], ah, bl[fn], acc[fm][fn]);
                    wmma::mma_sync(acc[fm][fn], al, bh[fn], acc[fm][fn]);
                }
            }
        }
    }
    __syncthreads();

    float* scr = (float*)&Ah[0][0] + wid * 320;
#pragma unroll
    for (int fm = 0; fm < 4; fm++)
#pragma unroll
        for (int fn = 0; fn < 2; fn++) {
            wmma::store_matrix_sync(scr, acc[fm][fn], 20, wmma::mem_row_major);
            __syncwarp();
#pragma unroll
            for (int u = 0; u < 8; u++) {
                int el = lane + u * 32;
                int r = el >> 4, c = el & 15;
                int gi = i0 + wn * 32 + fn * 16 + c;
                int gr = r0 + wm * 64 + fm * 16 + r;
                g_Z[(size_t)gr * EMB + gi] = fmaxf(scr[r * 20 + c] + g_bc[gi], 0.f);
            }
            __syncwarp();
        }
}

// ---------------- 4) final head ----------------
__global__ void k_final(const float* __restrict__ W3, const float* __restrict__ b3,
                        float* __restrict__ out) {
    __shared__ float red[8];
    int m = blockIdx.x;
    const float* z1 = g_Z + (size_t)m * 3 * EMB;
    const float* z2 = z1 + EMB;
    const float* zq = z1 + 2 * EMB;
    float s = 0.f;
    for (int i = threadIdx.x; i < EMB; i += 256) {
        float a = z1[i], b = z2[i], q = zq[i];
        s += W3[i] * a + W3[EMB + i] * b +
             W3[2 * EMB + i] * fabsf(a - b) +
             W3[3 * EMB + i] * fabsf(a - q) +
             W3[4 * EMB + i] * fabsf(b - q);
    }
#pragma unroll
    for (int off = 16; off; off >>= 1)
        s += __shfl_xor_sync(0xffffffffu, s, off);
    if ((threadIdx.x & 31) == 0) red[threadIdx.x >> 5] = s;
    __syncthreads();
    if (threadIdx.x == 0) {
        float t = 0.f;
#pragma unroll
        for (int w = 0; w < 8; w++) t += red[w];
        out[m] = fmaxf(t + b3[0], 0.f);
    }
}

// ---------------- launch ----------------
extern "C" void kernel_launch(void* const* d_in, const int* in_sizes, int n_in,
                              void* d_out, int out_size) {
    (void)in_sizes; (void)n_in; (void)out_size;
    const float* X  = (const float*)d_in[0];
    const float* Wa = (const float*)d_in[1];
    const float* va = (const float*)d_in[2];
    const float* W1 = (const float*)d_in[3];
    const float* b1 = (const float*)d_in[4];
    const float* W2 = (const float*)d_in[5];
    const float* b2 = (const float*)d_in[6];
    const float* W3 = (const float*)d_in[7];
    const float* b3 = (const float*)d_in[8];
    float* out = (float*)d_out;

    static int smem_set = 0;
    if (!smem_set) {
        cudaFuncSetAttribute(k_attend, cudaFuncAttributeMaxDynamicSharedMemorySize,
                             SMEM_DYN);
        smem_set = 1;
    }

    k_split<<<768, 256>>>(Wa);
    k_wc<<<dim3(12, 12), 256>>>(W1, W2);
    k_bc<<<96, 256>>>(W2, b1, b2);
    k_wcsplit<<<(EMB * EMB + 255) / 256, 256>>>();
    k_attend<<<MROWS, 512, SMEM_DYN>>>(X, va);
    k_mlp<<<dim3(24, 6), 256>>>();
    k_final<<<MROWS, 256>>>(W3, b3, out);
}